// round 1
// baseline (speedup 1.0000x reference)
#include <cuda_runtime.h>

#define LN_EPS 1e-12f

// Precomputed LN(W_rel) rows: 130 x 64 floats.
__device__ float g_lnrel[130 * 64];

// ---------------------------------------------------------------------------
// Kernel 0: prep. blocks 0..129: LN one row of W_rel -> g_lnrel.
//           blocks 130..193: LN one row of W_glob -> embd0 (x8 batch copies).
// ---------------------------------------------------------------------------
__global__ void k_prep(const float* __restrict__ W_rel,
                       const float* __restrict__ W_glob,
                       float* __restrict__ out0) {
    int blk = blockIdx.x, t = threadIdx.x;
    __shared__ float red[4];

    float x = (blk < 130) ? W_rel[blk * 64 + t]
                          : W_glob[(blk - 130) * 64 + t];
    float s = x, q = x * x;
    #pragma unroll
    for (int o = 16; o; o >>= 1) {
        s += __shfl_down_sync(0xffffffffu, s, o);
        q += __shfl_down_sync(0xffffffffu, q, o);
    }
    if ((t & 31) == 0) { red[(t >> 5) * 2] = s; red[(t >> 5) * 2 + 1] = q; }
    __syncthreads();
    float mean = (red[0] + red[2]) * (1.0f / 64.0f);
    float var  = (red[1] + red[3]) * (1.0f / 64.0f) - mean * mean;
    float inv  = rsqrtf(var + LN_EPS);
    float v = (x - mean) * inv;

    if (blk < 130) {
        g_lnrel[blk * 64 + t] = v;
    } else {
        int g = blk - 130;
        #pragma unroll
        for (int b = 0; b < 8; b++)
            out0[(b * 64 + g) * 64 + t] = v;
    }
}

// ---------------------------------------------------------------------------
// Kernel 2: embd2 fill. One block per (b,i): writes 512*64 floats (128 KB)
// contiguously; values are shared-memory lookups of precomputed LN(W_rel).
// Diagonal gets row 0 here; overwritten later by k_embd1's diag pass.
// ---------------------------------------------------------------------------
__global__ void __launch_bounds__(256) k_embd2(const int* __restrict__ tty,
                                               float4* __restrict__ out2) {
    __shared__ float lnrel[130 * 64];
    __shared__ int   sid[512];
    __shared__ int   stype[512];

    int b = blockIdx.x >> 9;
    int i = blockIdx.x & 511;
    int t = threadIdx.x;

    // stage LN(W_rel) table (33 KB) from L2
    for (int e = t; e < 130 * 16; e += 256)
        reinterpret_cast<float4*>(lnrel)[e] =
            reinterpret_cast<const float4*>(g_lnrel)[e];
    for (int j = t; j < 512; j += 256)
        stype[j] = tty[b * 512 + j];
    __syncthreads();

    int ti = stype[i];
    for (int j = t; j < 512; j += 256) {
        int id;
        if (i == 0)             id = (j == 0) ? 0 : 128;
        else if (j == 0)        id = 129;
        else if (stype[j] != ti) id = 64;
        else {
            int d = i - j;
            id = (d >= 0) ? ((d == 0) ? 0 : 128 - min(d, 63))
                          : min(-d, 63);
        }
        sid[j] = id * 16;  // float4 row offset
    }
    __syncthreads();

    const float4* ln4 = reinterpret_cast<const float4*>(lnrel);
    size_t base = (size_t)blockIdx.x * (512 * 16);
    #pragma unroll 4
    for (int e = t; e < 512 * 16; e += 256) {
        int j = e >> 4, d4 = e & 15;
        __stcs(&out2[base + e], ln4[sid[j] + d4]);
    }
}

// ---------------------------------------------------------------------------
// Kernel 1: embd1 (gather + LN) for 8 rows per block, then the diag pass:
// diag2 = preLN_embd1 @ W_diag^T + b_diag;  embd2[b,s,s,:] = LN(W_rel[0]+diag2)
// ---------------------------------------------------------------------------
__global__ void __launch_bounds__(256) k_embd1(
    const int* __restrict__ tok, const int* __restrict__ tty,
    const float* __restrict__ Wword, const float* __restrict__ Wtype,
    const float* __restrict__ Wabs,  const float* __restrict__ Wrel,
    const float* __restrict__ Wdiag, const float* __restrict__ bdiag,
    float* __restrict__ out1, float* __restrict__ out2) {

    __shared__ float sx[8][768];     // pre-LN rows
    __shared__ float sWd[64 * 65];   // W_diag chunk, padded
    __shared__ float wsum[8], wsq[8];
    __shared__ float sstat[2];

    int t = threadIdx.x;
    int warp = t >> 5, lane = t & 31;
    int row0 = blockIdx.x * 8;

    // ---- phase 1: gather + LN embd1 ----
    for (int r = 0; r < 8; r++) {
        int row = row0 + r;
        int s = row & 511;
        int tk = tok[row], ty = tty[row];
        const float* pw = Wword + (size_t)tk * 768;
        const float* pt = Wtype + (size_t)ty * 768;
        const float* pa = Wabs  + (size_t)s  * 768;
        float v0 = pw[t      ] + pt[t      ] + pa[t      ];
        float v1 = pw[t + 256] + pt[t + 256] + pa[t + 256];
        float v2 = pw[t + 512] + pt[t + 512] + pa[t + 512];
        sx[r][t] = v0; sx[r][t + 256] = v1; sx[r][t + 512] = v2;

        float s1 = v0 + v1 + v2;
        float q1 = v0 * v0 + v1 * v1 + v2 * v2;
        #pragma unroll
        for (int o = 16; o; o >>= 1) {
            s1 += __shfl_down_sync(0xffffffffu, s1, o);
            q1 += __shfl_down_sync(0xffffffffu, q1, o);
        }
        if (lane == 0) { wsum[warp] = s1; wsq[warp] = q1; }
        __syncthreads();
        if (t == 0) {
            float S = 0.f, Q = 0.f;
            #pragma unroll
            for (int w = 0; w < 8; w++) { S += wsum[w]; Q += wsq[w]; }
            float mean = S * (1.0f / 768.0f);
            float var  = Q * (1.0f / 768.0f) - mean * mean;
            sstat[0] = mean; sstat[1] = rsqrtf(var + LN_EPS);
        }
        __syncthreads();
        float mean = sstat[0], inv = sstat[1];
        float* o = out1 + (size_t)row * 768;
        o[t      ] = (v0 - mean) * inv;
        o[t + 256] = (v1 - mean) * inv;
        o[t + 512] = (v2 - mean) * inv;
        __syncthreads();  // protect wsum/sstat reuse next iteration
    }

    // ---- phase 2: diag2 matvec (warp = row; lane owns outputs lane, lane+32)
    float acc0 = 0.f, acc1 = 0.f;
    for (int c = 0; c < 12; c++) {
        __syncthreads();
        for (int e = t; e < 64 * 64; e += 256) {
            int k = e >> 6, dd = e & 63;
            sWd[k * 65 + dd] = Wdiag[(size_t)k * 768 + c * 64 + dd];
        }
        __syncthreads();
        const float* xr = &sx[warp][c * 64];
        #pragma unroll 8
        for (int dd = 0; dd < 64; dd++) {
            float xv = xr[dd];
            acc0 += xv * sWd[lane * 65 + dd];
            acc1 += xv * sWd[(lane + 32) * 65 + dd];
        }
    }

    int row = row0 + warp;
    int s = row & 511;
    float y0 = acc0 + Wrel[lane]      + bdiag[lane];
    float y1 = acc1 + Wrel[lane + 32] + bdiag[lane + 32];
    float S = y0 + y1, Q = y0 * y0 + y1 * y1;
    #pragma unroll
    for (int o = 16; o; o >>= 1) {
        S += __shfl_xor_sync(0xffffffffu, S, o);
        Q += __shfl_xor_sync(0xffffffffu, Q, o);
    }
    float mean = S * (1.0f / 64.0f);
    float inv  = rsqrtf(Q * (1.0f / 64.0f) - mean * mean + LN_EPS);
    float* od = out2 + ((size_t)row * 512 + s) * 64;
    od[lane]      = (y0 - mean) * inv;
    od[lane + 32] = (y1 - mean) * inv;
}

// ---------------------------------------------------------------------------
extern "C" void kernel_launch(void* const* d_in, const int* in_sizes, int n_in,
                              void* d_out, int out_size) {
    const int*   tok   = (const int*)d_in[0];
    const int*   tty   = (const int*)d_in[1];
    const float* Wword = (const float*)d_in[2];
    const float* Wtype = (const float*)d_in[3];
    const float* Wabs  = (const float*)d_in[4];
    const float* Wrel  = (const float*)d_in[5];
    const float* Wglob = (const float*)d_in[6];
    const float* Wdiag = (const float*)d_in[7];
    const float* bdiag = (const float*)d_in[8];

    float* out  = (float*)d_out;
    float* out0 = out;                         // [8,64,64]
    float* out1 = out0 + 8 * 64 * 64;          // [8,512,768]
    float* out2 = out1 + 8 * 512 * 768;        // [8,512,512,64]

    k_prep <<<194, 64>>>(Wrel, Wglob, out0);
    k_embd2<<<4096, 256>>>(tty, (float4*)out2);
    k_embd1<<<512, 256>>>(tok, tty, Wword, Wtype, Wabs, Wrel, Wdiag, bdiag,
                          out1, out2);
}

// round 2
// speedup vs baseline: 1.1438x; 1.1438x over previous
#include <cuda_runtime.h>

#define LN_EPS 1e-12f

struct SmemU {
    union {
        struct {                       // embd2 role
            float lnrel[130 * 64];     // 33280 B
            int   sid[2][512];         // 4096 B
            int   stype[512];          // 2048 B
        } e2;
        struct {                       // compute role
            float sx[8][768];          // 24576 B
            union {
                float sWd[64][65];     // 16640 B
                float sred[8][8][64];  // 16384 B
            };
            float sy[8][64];           // 2048 B
            float wsum[8], wsq[8];
            float stat[2];
        } e1;
    };
};

__global__ void __launch_bounds__(256) k_fused(
    const int* __restrict__ tok, const int* __restrict__ tty,
    const float* __restrict__ Wword, const float* __restrict__ Wtype,
    const float* __restrict__ Wabs,  const float* __restrict__ Wrel,
    const float* __restrict__ Wglob, const float* __restrict__ Wdiag,
    const float* __restrict__ bdiag,
    float* __restrict__ out0, float* __restrict__ out1,
    float* __restrict__ out2) {

    __shared__ SmemU sm;
    const int bid  = blockIdx.x;
    const int t    = threadIdx.x;
    const int warp = t >> 5, lane = t & 31;

    if ((bid % 5) != 4) {
        // ==================== embd2 role: 2048 blocks, 2 rows each =========
        const int eid = bid - bid / 5;
        const int R0  = eid * 2;            // global rows R0, R0+1 (same batch)
        const int b   = R0 >> 9;
        const int i0  = R0 & 511;

        // LN(W_rel) computed locally: warp-per-row, 17 passes
        for (int p = 0; p < 17; p++) {
            int row = p * 8 + warp;
            if (row < 130) {
                float x0 = Wrel[row * 64 + lane];
                float x1 = Wrel[row * 64 + 32 + lane];
                float s = x0 + x1, q = x0 * x0 + x1 * x1;
                #pragma unroll
                for (int o = 16; o; o >>= 1) {
                    s += __shfl_xor_sync(0xffffffffu, s, o);
                    q += __shfl_xor_sync(0xffffffffu, q, o);
                }
                float mean = s * (1.0f / 64.0f);
                float inv  = rsqrtf(q * (1.0f / 64.0f) - mean * mean + LN_EPS);
                sm.e2.lnrel[row * 64 + lane]      = (x0 - mean) * inv;
                sm.e2.lnrel[row * 64 + 32 + lane] = (x1 - mean) * inv;
            }
        }
        for (int j = t; j < 512; j += 256) sm.e2.stype[j] = tty[b * 512 + j];
        __syncthreads();

        for (int rr = 0; rr < 2; rr++) {
            int i  = i0 + rr;
            int ti = sm.e2.stype[i];
            for (int j = t; j < 512; j += 256) {
                int id;
                if (j == i)                      id = -1;          // diag: skip
                else if (i == 0)                 id = 128;
                else if (j == 0)                 id = 129;
                else if (sm.e2.stype[j] != ti)   id = 64;
                else {
                    int d = i - j;
                    id = (d > 0) ? 128 - min(d, 63) : min(-d, 63);
                }
                sm.e2.sid[rr][j] = (id < 0) ? -1 : id * 16;
            }
        }
        __syncthreads();

        const float4* ln4 = reinterpret_cast<const float4*>(sm.e2.lnrel);
        float4* outp = reinterpret_cast<float4*>(out2) + (size_t)R0 * (512 * 16);
        #pragma unroll 4
        for (int e = t; e < 2 * 512 * 16; e += 256) {
            int j  = (e >> 4) & 511;
            int rr = e >> 13;
            int d4 = e & 15;
            int s  = sm.e2.sid[rr][j];
            if (s >= 0) __stcs(&outp[e], ln4[s + d4]);
        }
        return;
    }

    // ==================== compute role: 512 blocks, 8 rows each ============
    const int cid  = bid / 5;
    const int row0 = cid * 8;

    // out0 duty: blocks 0..7 LN 8 rows of W_glob each, broadcast x8 batches
    if (cid < 8) {
        int g = cid * 8 + warp;
        float x0 = Wglob[g * 64 + lane];
        float x1 = Wglob[g * 64 + 32 + lane];
        float s = x0 + x1, q = x0 * x0 + x1 * x1;
        #pragma unroll
        for (int o = 16; o; o >>= 1) {
            s += __shfl_xor_sync(0xffffffffu, s, o);
            q += __shfl_xor_sync(0xffffffffu, q, o);
        }
        float mean = s * (1.0f / 64.0f);
        float inv  = rsqrtf(q * (1.0f / 64.0f) - mean * mean + LN_EPS);
        float v0 = (x0 - mean) * inv, v1 = (x1 - mean) * inv;
        #pragma unroll
        for (int bb = 0; bb < 8; bb++) {
            out0[(bb * 64 + g) * 64 + lane]      = v0;
            out0[(bb * 64 + g) * 64 + 32 + lane] = v1;
        }
    }

    // ---- phase 1: gather + LN embd1 (8 rows) ----
    for (int r = 0; r < 8; r++) {
        int row = row0 + r;
        int s   = row & 511;
        int tk  = tok[row], ty = tty[row];
        const float* pw = Wword + (size_t)tk * 768;
        const float* pt = Wtype + (size_t)ty * 768;
        const float* pa = Wabs  + (size_t)s  * 768;
        float v0 = pw[t      ] + pt[t      ] + pa[t      ];
        float v1 = pw[t + 256] + pt[t + 256] + pa[t + 256];
        float v2 = pw[t + 512] + pt[t + 512] + pa[t + 512];
        sm.e1.sx[r][t] = v0; sm.e1.sx[r][t + 256] = v1; sm.e1.sx[r][t + 512] = v2;

        float s1 = v0 + v1 + v2;
        float q1 = v0 * v0 + v1 * v1 + v2 * v2;
        #pragma unroll
        for (int o = 16; o; o >>= 1) {
            s1 += __shfl_down_sync(0xffffffffu, s1, o);
            q1 += __shfl_down_sync(0xffffffffu, q1, o);
        }
        if (lane == 0) { sm.e1.wsum[warp] = s1; sm.e1.wsq[warp] = q1; }
        __syncthreads();
        if (t == 0) {
            float S = 0.f, Q = 0.f;
            #pragma unroll
            for (int w = 0; w < 8; w++) { S += sm.e1.wsum[w]; Q += sm.e1.wsq[w]; }
            float mean = S * (1.0f / 768.0f);
            float var  = Q * (1.0f / 768.0f) - mean * mean;
            sm.e1.stat[0] = mean; sm.e1.stat[1] = rsqrtf(var + LN_EPS);
        }
        __syncthreads();
        float mean = sm.e1.stat[0], inv = sm.e1.stat[1];
        float* o = out1 + (size_t)row * 768;
        o[t      ] = (v0 - mean) * inv;
        o[t + 256] = (v1 - mean) * inv;
        o[t + 512] = (v2 - mean) * inv;
        __syncthreads();
    }

    // ---- phase 2: diag GEMV, 8-row register blocking, warp k-split ----
    float acc0[8], acc1[8];
    #pragma unroll
    for (int r = 0; r < 8; r++) { acc0[r] = 0.f; acc1[r] = 0.f; }

    for (int c = 0; c < 12; c++) {
        __syncthreads();
        // stage chunk: sWd[k_local][d] = Wdiag[d][c*64+k_local] (coalesced reads)
        for (int e = t; e < 64 * 64; e += 256) {
            int k = e & 63, d = e >> 6;
            sm.e1.sWd[k][d] = Wdiag[(size_t)d * 768 + c * 64 + k];
        }
        __syncthreads();
        int kbase = warp * 8;
        #pragma unroll
        for (int kk = 0; kk < 8; kk++) {
            float w0 = sm.e1.sWd[kbase + kk][lane];
            float w1 = sm.e1.sWd[kbase + kk][lane + 32];
            int kg = c * 64 + kbase + kk;
            #pragma unroll
            for (int r = 0; r < 8; r++) {
                float xv = sm.e1.sx[r][kg];
                acc0[r] += xv * w0;
                acc1[r] += xv * w1;
            }
        }
    }

    // cross-warp reduction
    __syncthreads();
    #pragma unroll
    for (int r = 0; r < 8; r++) {
        sm.e1.sred[warp][r][lane]      = acc0[r];
        sm.e1.sred[warp][r][lane + 32] = acc1[r];
    }
    __syncthreads();
    for (int o = t; o < 512; o += 256) {
        int r = o >> 6, d = o & 63;
        float s = 0.f;
        #pragma unroll
        for (int w = 0; w < 8; w++) s += sm.e1.sred[w][r][d];
        sm.e1.sy[r][d] = s + Wrel[d] + bdiag[d];
    }
    __syncthreads();

    // LN per diag row + store to embd2 diagonal
    {
        float y0 = sm.e1.sy[warp][lane];
        float y1 = sm.e1.sy[warp][lane + 32];
        float S = y0 + y1, Q = y0 * y0 + y1 * y1;
        #pragma unroll
        for (int o = 16; o; o >>= 1) {
            S += __shfl_xor_sync(0xffffffffu, S, o);
            Q += __shfl_xor_sync(0xffffffffu, Q, o);
        }
        float mean = S * (1.0f / 64.0f);
        float inv  = rsqrtf(Q * (1.0f / 64.0f) - mean * mean + LN_EPS);
        int row = row0 + warp;
        int s   = row & 511;
        float* od = out2 + ((size_t)row * 512 + s) * 64;
        od[lane]      = (y0 - mean) * inv;
        od[lane + 32] = (y1 - mean) * inv;
    }
}

// ---------------------------------------------------------------------------
extern "C" void kernel_launch(void* const* d_in, const int* in_sizes, int n_in,
                              void* d_out, int out_size) {
    const int*   tok   = (const int*)d_in[0];
    const int*   tty   = (const int*)d_in[1];
    const float* Wword = (const float*)d_in[2];
    const float* Wtype = (const float*)d_in[3];
    const float* Wabs  = (const float*)d_in[4];
    const float* Wrel  = (const float*)d_in[5];
    const float* Wglob = (const float*)d_in[6];
    const float* Wdiag = (const float*)d_in[7];
    const float* bdiag = (const float*)d_in[8];

    float* out  = (float*)d_out;
    float* out0 = out;                      // [8,64,64]
    float* out1 = out0 + 8 * 64 * 64;       // [8,512,768]
    float* out2 = out1 + 8 * 512 * 768;     // [8,512,512,64]

    k_fused<<<2560, 256>>>(tok, tty, Wword, Wtype, Wabs, Wrel, Wglob, Wdiag,
                           bdiag, out0, out1, out2);
}